// round 8
// baseline (speedup 1.0000x reference)
#include <cuda_runtime.h>
#include <cstdint>

#define NB 4
#define NL 512
#define ND 128
#define L2E 1.4426950408889634f

// Scratch (static device arrays)
__device__ float g_a [NB*NL*ND];     // 1 MB
__device__ float g_bm[NB*NL*ND];     // 1 MB
__device__ float g_sc[NB*NL*NL];     // 4 MB raw scores
__device__ float g_ms [NB*NL];       // per-(b,j): max_i(score) * log2(e)
__device__ float g_inv[NB*NL];       // per-(b,j): 1 / sum_i exp

__device__ __forceinline__ float tanh_fast(float x) {
    float y; asm("tanh.approx.f32 %0, %1;" : "=f"(y) : "f"(x)); return y;
}
__device__ __forceinline__ float ex2_fast(float x) {
    float y; asm("ex2.approx.ftz.f32 %0, %1;" : "=f"(y) : "f"(x)); return y;
}
__device__ __forceinline__ float rcp_fast(float x) {
    float y; asm("rcp.approx.ftz.f32 %0, %1;" : "=f"(y) : "f"(x)); return y;
}
__device__ __forceinline__ void cp_async16(unsigned int dst, const void* src) {
    asm volatile("cp.async.cg.shared.global [%0], [%1], 16;\n" :: "r"(dst), "l"(src));
}
__device__ __forceinline__ unsigned int smem_u32(const void* p) {
    unsigned int a;
    asm("{ .reg .u64 t; cvta.to.shared.u64 t, %1; cvt.u32.u64 %0, t; }" : "=r"(a) : "l"(p));
    return a;
}

// ---------------------------------------------------------------------------
// Kernel A: projections (transposed weight contraction):
//   a [bl][e] = sum_d hs[bl][d] * W_attn[e, d]
//   bm[bl][e] = sum_d hs[bl][d] * W_attn[e, 128 + d]
// grid (64 row-tiles, 4 chunks of the 256 fused outputs), 256 threads.
// ---------------------------------------------------------------------------
__global__ void proj_kernel(const float* __restrict__ hs,
                            const float* __restrict__ W) {
    __shared__ float hs_s[32 * 128];    // 16 KB
    __shared__ float W_s [128 * 64];    // 32 KB, [d][swizzled c]
    const int rowbase = blockIdx.x * 32;
    const int colbase = blockIdx.y * 64;
    const int tid = threadIdx.x;

    for (int k = tid; k < 32 * 128; k += 256)
        hs_s[k] = hs[(rowbase + (k >> 7)) * 128 + (k & 127)];
    for (int k = tid; k < 64 * 128; k += 256) {
        int c = k >> 7, d = k & 127;
        int e = colbase + c;
        float w = (e < 128) ? W[e * 256 + d] : W[(e - 128) * 256 + 128 + d];
        W_s[d * 64 + ((c + d) & 63)] = w;
    }
    __syncthreads();

    const int ty = tid >> 5, tx = tid & 31;
    float acc[4][2] = {};
#pragma unroll 4
    for (int k = 0; k < 128; k++) {
        float w0 = W_s[k * 64 + ((tx      + k) & 63)];
        float w1 = W_s[k * 64 + ((tx + 32 + k) & 63)];
#pragma unroll
        for (int rr = 0; rr < 4; rr++) {
            float h = hs_s[(ty * 4 + rr) * 128 + k];   // warp broadcast
            acc[rr][0] += h * w0;
            acc[rr][1] += h * w1;
        }
    }
#pragma unroll
    for (int rr = 0; rr < 4; rr++) {
        int row = rowbase + ty * 4 + rr;
#pragma unroll
        for (int cc = 0; cc < 2; cc++) {
            int e = colbase + tx + cc * 32;
            float val = acc[rr][cc];
            if (e < 128) g_a [row * 128 + e]         = val;
            else         g_bm[row * 128 + (e - 128)] = val;
        }
    }
}

// ---------------------------------------------------------------------------
// Kernel B (MUFU-bound): scores[b,i,j] = sum_d v[d]*tanh(a[b,i,d]+bm[b,j,d])
// grid (16,16,4), 256 threads, 2x2 micro-tile, float4 smem (pitch 33 vec4)
// ---------------------------------------------------------------------------
__global__ void score_kernel(const float* __restrict__ v) {
    __shared__ float4 a_s[32 * 33];     // 16.9 KB, row pitch 33 float4
    __shared__ float4 b_s[32 * 33];
    __shared__ float4 v_s[32];
    const int bi = blockIdx.z;
    const int i0 = blockIdx.x * 32, j0 = blockIdx.y * 32;
    const int tid = threadIdx.x;

    const float4* ga4 = (const float4*)g_a;
    const float4* gb4 = (const float4*)g_bm;
    for (int k = tid; k < 32 * 32; k += 256) {
        int r = k >> 5, q = k & 31;
        a_s[r * 33 + q] = ga4[(bi * NL + i0 + r) * 32 + q];
        b_s[r * 33 + q] = gb4[(bi * NL + j0 + r) * 32 + q];
    }
    if (tid < 32) v_s[tid] = ((const float4*)v)[tid];
    __syncthreads();

    const int ty = tid >> 4, tx = tid & 15;
    float acc00 = 0.f, acc01 = 0.f, acc10 = 0.f, acc11 = 0.f;
#pragma unroll 8
    for (int q = 0; q < 32; q++) {
        float4 vq = v_s[q];
        float4 a0 = a_s[ ty       * 33 + q];
        float4 a1 = a_s[(ty + 16) * 33 + q];
        float4 b0 = b_s[ tx       * 33 + q];
        float4 b1 = b_s[(tx + 16) * 33 + q];
        acc00 += vq.x * tanh_fast(a0.x + b0.x);
        acc00 += vq.y * tanh_fast(a0.y + b0.y);
        acc00 += vq.z * tanh_fast(a0.z + b0.z);
        acc00 += vq.w * tanh_fast(a0.w + b0.w);
        acc01 += vq.x * tanh_fast(a0.x + b1.x);
        acc01 += vq.y * tanh_fast(a0.y + b1.y);
        acc01 += vq.z * tanh_fast(a0.z + b1.z);
        acc01 += vq.w * tanh_fast(a0.w + b1.w);
        acc10 += vq.x * tanh_fast(a1.x + b0.x);
        acc10 += vq.y * tanh_fast(a1.y + b0.y);
        acc10 += vq.z * tanh_fast(a1.z + b0.z);
        acc10 += vq.w * tanh_fast(a1.w + b0.w);
        acc11 += vq.x * tanh_fast(a1.x + b1.x);
        acc11 += vq.y * tanh_fast(a1.y + b1.y);
        acc11 += vq.z * tanh_fast(a1.z + b1.z);
        acc11 += vq.w * tanh_fast(a1.w + b1.w);
    }
    float* sp = g_sc + (size_t)bi * NL * NL;
    sp[(i0 + ty     ) * NL + j0 + tx     ] = acc00;
    sp[(i0 + ty     ) * NL + j0 + tx + 16] = acc01;
    sp[(i0 + ty + 16) * NL + j0 + tx     ] = acc10;
    sp[(i0 + ty + 16) * NL + j0 + tx + 16] = acc11;
}

// ---------------------------------------------------------------------------
// Kernel C: per-(b,j) softmax stats over i (axis=1). Writes m* = max*log2e
// and inv = 1/sum(exp). out_kernel reconstructs weights on the fly.
// ---------------------------------------------------------------------------
__global__ void stat_kernel() {
    const int bi = blockIdx.y;
    const int l  = threadIdx.x & 31;         // j lane
    const int g  = threadIdx.x >> 5;         // i-group 0..7
    const int j  = blockIdx.x * 32 + l;
    const float* sp = g_sc + (size_t)bi * NL * NL + j;
    __shared__ float red[8][32];

    float m = -1e30f;
#pragma unroll 8
    for (int i = g; i < NL; i += 8) m = fmaxf(m, sp[i * NL]);
    red[g][l] = m;
    __syncthreads();
    if (g == 0) {
#pragma unroll
        for (int r = 1; r < 8; r++) m = fmaxf(m, red[r][l]);
        red[0][l] = m;
    }
    __syncthreads();
    const float ms = red[0][l] * L2E;

    float s = 0.f;
#pragma unroll 8
    for (int i = g; i < NL; i += 8) s += ex2_fast(sp[i * NL] * L2E - ms);
    __syncthreads();
    red[g][l] = s;
    __syncthreads();
    if (g == 0) {
#pragma unroll
        for (int r = 1; r < 8; r++) s += red[r][l];
        g_ms [bi * NL + j] = ms;
        g_inv[bi * NL + j] = rcp_fast(s);
    }
}

// ---------------------------------------------------------------------------
// Kernel D v4: out[b,i,d] = sum_j softmax_w[b,i,j] * hs[b,j,d]
// Block: 16 i x 64 d, 256 threads, grid 256 (all 148 SMs, 2 CTAs on most).
// Warp wid covers all 16 rows x 8 d (d-seg = wid*8).
// Lane: r = lane>>1 (row 0..15), c = lane&1 (float4 half).
// Per j per warp: 1 LDS.32 w (16 distinct, 2x bcast) + 1 LDS.128 h (2 distinct)
//                 + 4 FFMA -> FMA/crossbar balanced at 2 CTAs/SM.
// w staged transposed [j][row] pitch 17 (17 coprime 32 -> conflict-free both
// ways); h double-buffered via cp.async; softmax stats read per-chunk from
// global (prefetched). smem 20.4 KB, low regs.
// ---------------------------------------------------------------------------
__global__ void __launch_bounds__(256, 2)
out_kernel(const float* __restrict__ hs, float* __restrict__ out) {
    __shared__ float w_s[2][32 * 17];                 // 4.25 KB [j][row]
    __shared__ __align__(16) float h_s[2][32 * 64];   // 16 KB   [j][d]
    const int i0 = blockIdx.x * 16;
    const int bi = blockIdx.y;
    const int d0 = blockIdx.z * 64;
    const int tid  = threadIdx.x;
    const int wid  = tid >> 5;
    const int lane = tid & 31;
    const int r = lane >> 1;          // row 0..15
    const int c = lane & 1;           // float4 half
    const int dfrag = wid * 8 + c * 4;
    const int myrow = tid >> 5;       // unused alias guard

    const float* scb  = g_sc  + (size_t)bi * NL * NL;
    const float* msb  = g_ms  + bi * NL;
    const float* invb = g_inv + bi * NL;

    const int jl = tid & 31;          // this thread's j-lane within a chunk
    const int wrow = tid >> 5;        // rows 0..7 for s=0, +8 for s=1

    // ---- prologue: chunk 0 ----
    float rw0, rw1, rm, ri;
    rw0 = scb[(i0 + wrow    ) * NL + jl];
    rw1 = scb[(i0 + wrow + 8) * NL + jl];
    rm  = msb [jl];
    ri  = invb[jl];
#pragma unroll
    for (int s = 0; s < 2; s++) {
        int k = tid + 256 * s;                 // k = j*16 + seg
        int j = k >> 4, seg = k & 15;
        cp_async16(smem_u32(&h_s[0][j * 64 + seg * 4]),
                   &hs[(bi * NL + j) * ND + d0 + seg * 4]);
    }
    asm volatile("cp.async.commit_group;\n" ::: "memory");
    w_s[0][jl * 17 + wrow    ] = ex2_fast(rw0 * L2E - rm) * ri;
    w_s[0][jl * 17 + wrow + 8] = ex2_fast(rw1 * L2E - rm) * ri;
    asm volatile("cp.async.wait_group 0;\n" ::: "memory");
    __syncthreads();

    float4 acc = make_float4(0.f, 0.f, 0.f, 0.f);

    int p = 0;
    for (int ch = 0; ch < 16; ch++) {
        const int jn = (ch + 1) * 32;
        if (ch < 15) {
            // prefetch next chunk's raw w + stats (regs) and h (cp.async)
            rw0 = scb[(i0 + wrow    ) * NL + jn + jl];
            rw1 = scb[(i0 + wrow + 8) * NL + jn + jl];
            rm  = msb [jn + jl];
            ri  = invb[jn + jl];
#pragma unroll
            for (int s = 0; s < 2; s++) {
                int k = tid + 256 * s;
                int j = k >> 4, seg = k & 15;
                cp_async16(smem_u32(&h_s[p ^ 1][j * 64 + seg * 4]),
                           &hs[(bi * NL + jn + j) * ND + d0 + seg * 4]);
            }
            asm volatile("cp.async.commit_group;\n" ::: "memory");
        }

        // compute current chunk
        const float* wp = w_s[p];
        const float* hp = h_s[p];
#pragma unroll 8
        for (int j = 0; j < 32; j++) {
            float wf = wp[j * 17 + r];                          // 64B/warp
            float4 hf = *(const float4*)&hp[j * 64 + dfrag];    // 32B/warp
            acc.x += wf * hf.x;  acc.y += wf * hf.y;
            acc.z += wf * hf.z;  acc.w += wf * hf.w;
        }

        if (ch < 15) {
            w_s[p ^ 1][jl * 17 + wrow    ] = ex2_fast(rw0 * L2E - rm) * ri;
            w_s[p ^ 1][jl * 17 + wrow + 8] = ex2_fast(rw1 * L2E - rm) * ri;
            asm volatile("cp.async.wait_group 0;\n" ::: "memory");
            __syncthreads();
        }
        p ^= 1;
    }

    (void)myrow;
    *(float4*)&out[((size_t)bi * NL + i0 + r) * ND + d0 + dfrag] = acc;
}

// ---------------------------------------------------------------------------
extern "C" void kernel_launch(void* const* d_in, const int* in_sizes, int n_in,
                              void* d_out, int out_size) {
    const float* hs = (const float*)d_in[0];   // (4,512,128)
    const float* W  = (const float*)d_in[1];   // (128,256)
    const float* v  = (const float*)d_in[2];   // (128,)
    float* out = (float*)d_out;                // (4,512,128)

    proj_kernel <<<dim3(64, 4),     256>>>(hs, W);
    score_kernel<<<dim3(16, 16, 4), 256>>>(v);
    stat_kernel <<<dim3(16, 4),     256>>>();
    out_kernel  <<<dim3(32, 4, 2),  256>>>(hs, out);
}

// round 9
// speedup vs baseline: 1.0290x; 1.0290x over previous
#include <cuda_runtime.h>
#include <cstdint>

#define NB 4
#define NL 512
#define ND 128
#define L2E 1.4426950408889634f

// Scratch (static device arrays)
__device__ float g_a [NB*NL*ND];     // 1 MB
__device__ float g_bm[NB*NL*ND];     // 1 MB
__device__ float g_sc[NB*NL*NL];     // 4 MB raw scores
__device__ float g_ms [NB*NL];       // per-(b,j): max_i(score) * log2(e)
__device__ float g_inv[NB*NL];       // per-(b,j): 1 / sum_i exp
__device__ float g_p0 [NB*NL*ND];    // 1 MB split-K partial (j 0..255)
__device__ float g_p1 [NB*NL*ND];    // 1 MB split-K partial (j 256..511)

__device__ __forceinline__ float tanh_fast(float x) {
    float y; asm("tanh.approx.f32 %0, %1;" : "=f"(y) : "f"(x)); return y;
}
__device__ __forceinline__ float ex2_fast(float x) {
    float y; asm("ex2.approx.ftz.f32 %0, %1;" : "=f"(y) : "f"(x)); return y;
}
__device__ __forceinline__ float rcp_fast(float x) {
    float y; asm("rcp.approx.ftz.f32 %0, %1;" : "=f"(y) : "f"(x)); return y;
}
__device__ __forceinline__ void cp_async16(unsigned int dst, const void* src) {
    asm volatile("cp.async.cg.shared.global [%0], [%1], 16;\n" :: "r"(dst), "l"(src));
}
__device__ __forceinline__ unsigned int smem_u32(const void* p) {
    unsigned int a;
    asm("{ .reg .u64 t; cvta.to.shared.u64 t, %1; cvt.u32.u64 %0, t; }" : "=r"(a) : "l"(p));
    return a;
}

// ---------------------------------------------------------------------------
// Kernel A: projections (transposed weight contraction):
//   a [bl][e] = sum_d hs[bl][d] * W_attn[e, d]
//   bm[bl][e] = sum_d hs[bl][d] * W_attn[e, 128 + d]
// ---------------------------------------------------------------------------
__global__ void proj_kernel(const float* __restrict__ hs,
                            const float* __restrict__ W) {
    __shared__ float hs_s[32 * 128];    // 16 KB
    __shared__ float W_s [128 * 64];    // 32 KB, [d][swizzled c]
    const int rowbase = blockIdx.x * 32;
    const int colbase = blockIdx.y * 64;
    const int tid = threadIdx.x;

    for (int k = tid; k < 32 * 128; k += 256)
        hs_s[k] = hs[(rowbase + (k >> 7)) * 128 + (k & 127)];
    for (int k = tid; k < 64 * 128; k += 256) {
        int c = k >> 7, d = k & 127;
        int e = colbase + c;
        float w = (e < 128) ? W[e * 256 + d] : W[(e - 128) * 256 + 128 + d];
        W_s[d * 64 + ((c + d) & 63)] = w;
    }
    __syncthreads();

    const int ty = tid >> 5, tx = tid & 31;
    float acc[4][2] = {};
#pragma unroll 4
    for (int k = 0; k < 128; k++) {
        float w0 = W_s[k * 64 + ((tx      + k) & 63)];
        float w1 = W_s[k * 64 + ((tx + 32 + k) & 63)];
#pragma unroll
        for (int rr = 0; rr < 4; rr++) {
            float h = hs_s[(ty * 4 + rr) * 128 + k];   // warp broadcast
            acc[rr][0] += h * w0;
            acc[rr][1] += h * w1;
        }
    }
#pragma unroll
    for (int rr = 0; rr < 4; rr++) {
        int row = rowbase + ty * 4 + rr;
#pragma unroll
        for (int cc = 0; cc < 2; cc++) {
            int e = colbase + tx + cc * 32;
            float val = acc[rr][cc];
            if (e < 128) g_a [row * 128 + e]         = val;
            else         g_bm[row * 128 + (e - 128)] = val;
        }
    }
}

// ---------------------------------------------------------------------------
// Kernel B (MUFU-bound): scores[b,i,j] = sum_d v[d]*tanh(a[b,i,d]+bm[b,j,d])
// grid (16,16,4), 256 threads, 2x2 micro-tile, float4 smem (pitch 33 vec4)
// ---------------------------------------------------------------------------
__global__ void score_kernel(const float* __restrict__ v) {
    __shared__ float4 a_s[32 * 33];     // 16.9 KB, row pitch 33 float4
    __shared__ float4 b_s[32 * 33];
    __shared__ float4 v_s[32];
    const int bi = blockIdx.z;
    const int i0 = blockIdx.x * 32, j0 = blockIdx.y * 32;
    const int tid = threadIdx.x;

    const float4* ga4 = (const float4*)g_a;
    const float4* gb4 = (const float4*)g_bm;
    for (int k = tid; k < 32 * 32; k += 256) {
        int r = k >> 5, q = k & 31;
        a_s[r * 33 + q] = ga4[(bi * NL + i0 + r) * 32 + q];
        b_s[r * 33 + q] = gb4[(bi * NL + j0 + r) * 32 + q];
    }
    if (tid < 32) v_s[tid] = ((const float4*)v)[tid];
    __syncthreads();

    const int ty = tid >> 4, tx = tid & 15;
    float acc00 = 0.f, acc01 = 0.f, acc10 = 0.f, acc11 = 0.f;
#pragma unroll 8
    for (int q = 0; q < 32; q++) {
        float4 vq = v_s[q];
        float4 a0 = a_s[ ty       * 33 + q];
        float4 a1 = a_s[(ty + 16) * 33 + q];
        float4 b0 = b_s[ tx       * 33 + q];
        float4 b1 = b_s[(tx + 16) * 33 + q];
        acc00 += vq.x * tanh_fast(a0.x + b0.x);
        acc00 += vq.y * tanh_fast(a0.y + b0.y);
        acc00 += vq.z * tanh_fast(a0.z + b0.z);
        acc00 += vq.w * tanh_fast(a0.w + b0.w);
        acc01 += vq.x * tanh_fast(a0.x + b1.x);
        acc01 += vq.y * tanh_fast(a0.y + b1.y);
        acc01 += vq.z * tanh_fast(a0.z + b1.z);
        acc01 += vq.w * tanh_fast(a0.w + b1.w);
        acc10 += vq.x * tanh_fast(a1.x + b0.x);
        acc10 += vq.y * tanh_fast(a1.y + b0.y);
        acc10 += vq.z * tanh_fast(a1.z + b0.z);
        acc10 += vq.w * tanh_fast(a1.w + b0.w);
        acc11 += vq.x * tanh_fast(a1.x + b1.x);
        acc11 += vq.y * tanh_fast(a1.y + b1.y);
        acc11 += vq.z * tanh_fast(a1.z + b1.z);
        acc11 += vq.w * tanh_fast(a1.w + b1.w);
    }
    float* sp = g_sc + (size_t)bi * NL * NL;
    sp[(i0 + ty     ) * NL + j0 + tx     ] = acc00;
    sp[(i0 + ty     ) * NL + j0 + tx + 16] = acc01;
    sp[(i0 + ty + 16) * NL + j0 + tx     ] = acc10;
    sp[(i0 + ty + 16) * NL + j0 + tx + 16] = acc11;
}

// ---------------------------------------------------------------------------
// Kernel C: per-(b,j) softmax stats over i (axis=1).
// ---------------------------------------------------------------------------
__global__ void stat_kernel() {
    const int bi = blockIdx.y;
    const int l  = threadIdx.x & 31;         // j lane
    const int g  = threadIdx.x >> 5;         // i-group 0..7
    const int j  = blockIdx.x * 32 + l;
    const float* sp = g_sc + (size_t)bi * NL * NL + j;
    __shared__ float red[8][32];

    float m = -1e30f;
#pragma unroll 8
    for (int i = g; i < NL; i += 8) m = fmaxf(m, sp[i * NL]);
    red[g][l] = m;
    __syncthreads();
    if (g == 0) {
#pragma unroll
        for (int r = 1; r < 8; r++) m = fmaxf(m, red[r][l]);
        red[0][l] = m;
    }
    __syncthreads();
    const float ms = red[0][l] * L2E;

    float s = 0.f;
#pragma unroll 8
    for (int i = g; i < NL; i += 8) s += ex2_fast(sp[i * NL] * L2E - ms);
    __syncthreads();
    red[g][l] = s;
    __syncthreads();
    if (g == 0) {
#pragma unroll
        for (int r = 1; r < 8; r++) s += red[r][l];
        g_ms [bi * NL + j] = ms;
        g_inv[bi * NL + j] = rcp_fast(s);
    }
}

// ---------------------------------------------------------------------------
// Kernel D v5: split-K version of the v3 fragment kernel.
// partial[b,i,d] = sum_{j in half} w[b,i,j] * hs[b,j,d]
// Block: 32 i x 64 d x 256 j (half), 256 threads, grid (16,4,4) = 256 blocks
//   blockIdx.z: bit0 = j-half, bit1 = d-half  -> 2 CTAs/SM on most SMs.
// Warp covers 32 rows x 8 d; lane (r=lane>>1, c=lane&1): 2 rows x float4.
// Per j per warp: 1 LDS.64 w + 1 LDS.128 h + 8 FFMA (v3's proven balance).
// ---------------------------------------------------------------------------
__global__ void __launch_bounds__(256, 2)
out_kernel(const float* __restrict__ hs) {
    __shared__ float ms_s [256];                      // 1 KB (this j-half)
    __shared__ float inv_s[256];                      // 1 KB
    __shared__ float w_s[2][32 * 34];                 // 8.5 KB  [j][row] pitch 34
    __shared__ __align__(16) float h_s[2][32 * 64];   // 16 KB   [j][d]
    const int i0 = blockIdx.x * 32;
    const int bi = blockIdx.y;
    const int jb = (blockIdx.z & 1) * 256;            // j-half base
    const int d0 = (blockIdx.z >> 1) * 64;            // d-half base
    const int tid  = threadIdx.x;
    const int wid  = tid >> 5;
    const int lane = tid & 31;
    const int r = lane >> 1;          // row-pair index 0..15
    const int c = lane & 1;           // float4 column 0..1
    const int dfrag = wid * 8 + c * 4;

    for (int k = tid; k < 256; k += 256) {
        ms_s [k] = g_ms [bi * NL + jb + k];
        inv_s[k] = g_inv[bi * NL + jb + k];
    }

    const float* scb = g_sc + (size_t)bi * NL * NL + jb;

    // ---- prologue: chunk 0 ----
    float rw[4];
#pragma unroll
    for (int s = 0; s < 4; s++) {
        int k = tid + 256 * s;                 // k = row*32 + j (coalesced over j)
        rw[s] = scb[(i0 + (k >> 5)) * NL + (k & 31)];
    }
#pragma unroll
    for (int s = 0; s < 2; s++) {
        int k = tid + 256 * s;                 // k = j*16 + seg
        int j = k >> 4, seg = k & 15;
        cp_async16(smem_u32(&h_s[0][j * 64 + seg * 4]),
                   &hs[(bi * NL + jb + j) * ND + d0 + seg * 4]);
    }
    asm volatile("cp.async.commit_group;\n" ::: "memory");
    __syncthreads();                            // ms_s/inv_s visible
#pragma unroll
    for (int s = 0; s < 4; s++) {
        int k = tid + 256 * s;
        int row = k >> 5, j = k & 31;
        w_s[0][j * 34 + row] = ex2_fast(rw[s] * L2E - ms_s[j]) * inv_s[j];
    }
    asm volatile("cp.async.wait_group 0;\n" ::: "memory");
    __syncthreads();

    float4 acc0 = make_float4(0.f, 0.f, 0.f, 0.f);
    float4 acc1 = make_float4(0.f, 0.f, 0.f, 0.f);

    int p = 0;
    for (int ch = 0; ch < 8; ch++) {
        const int jn = (ch + 1) * 32;
        if (ch < 7) {
#pragma unroll
            for (int s = 0; s < 4; s++) {
                int k = tid + 256 * s;
                rw[s] = scb[(i0 + (k >> 5)) * NL + jn + (k & 31)];
            }
#pragma unroll
            for (int s = 0; s < 2; s++) {
                int k = tid + 256 * s;
                int j = k >> 4, seg = k & 15;
                cp_async16(smem_u32(&h_s[p ^ 1][j * 64 + seg * 4]),
                           &hs[(bi * NL + jb + jn + j) * ND + d0 + seg * 4]);
            }
            asm volatile("cp.async.commit_group;\n" ::: "memory");
        }

        const float* wp = w_s[p];
        const float* hp = h_s[p];
#pragma unroll 8
        for (int j = 0; j < 32; j++) {
            float2 wf = *(const float2*)&wp[j * 34 + r * 2];   // 128B/warp
            float4 hf = *(const float4*)&hp[j * 64 + dfrag];   // 32B/warp
            acc0.x += wf.x * hf.x;  acc0.y += wf.x * hf.y;
            acc0.z += wf.x * hf.z;  acc0.w += wf.x * hf.w;
            acc1.x += wf.y * hf.x;  acc1.y += wf.y * hf.y;
            acc1.z += wf.y * hf.z;  acc1.w += wf.y * hf.w;
        }

        if (ch < 7) {
#pragma unroll
            for (int s = 0; s < 4; s++) {
                int k = tid + 256 * s;
                int row = k >> 5, j = k & 31;
                w_s[p ^ 1][j * 34 + row] =
                    ex2_fast(rw[s] * L2E - ms_s[jn + j]) * inv_s[jn + j];
            }
            asm volatile("cp.async.wait_group 0;\n" ::: "memory");
            __syncthreads();
        }
        p ^= 1;
    }

    float* pb = ((blockIdx.z & 1) ? g_p1 : g_p0)
              + ((size_t)bi * NL + i0 + r * 2) * ND + d0 + dfrag;
    *(float4*)&pb[0]  = acc0;
    *(float4*)&pb[ND] = acc1;
}

// ---------------------------------------------------------------------------
// Kernel E: out = p0 + p1  (1 MB, float4). grid 256 x 256 threads.
// ---------------------------------------------------------------------------
__global__ void reduce_kernel(float* __restrict__ out) {
    int idx = blockIdx.x * 256 + threadIdx.x;    // float4 index, 65536 total
    float4 a = ((const float4*)g_p0)[idx];
    float4 b = ((const float4*)g_p1)[idx];
    float4 r;
    r.x = a.x + b.x;  r.y = a.y + b.y;
    r.z = a.z + b.z;  r.w = a.w + b.w;
    ((float4*)out)[idx] = r;
}

// ---------------------------------------------------------------------------
extern "C" void kernel_launch(void* const* d_in, const int* in_sizes, int n_in,
                              void* d_out, int out_size) {
    const float* hs = (const float*)d_in[0];   // (4,512,128)
    const float* W  = (const float*)d_in[1];   // (128,256)
    const float* v  = (const float*)d_in[2];   // (128,)
    float* out = (float*)d_out;                // (4,512,128)

    proj_kernel  <<<dim3(64, 4),     256>>>(hs, W);
    score_kernel <<<dim3(16, 16, 4), 256>>>(v);
    stat_kernel  <<<dim3(16, 4),     256>>>();
    out_kernel   <<<dim3(16, 4, 4),  256>>>(hs);
    reduce_kernel<<<256,             256>>>(out);
}

// round 10
// speedup vs baseline: 1.0909x; 1.0601x over previous
#include <cuda_runtime.h>
#include <cstdint>

#define NB 4
#define NL 512
#define ND 128
#define L2E 1.4426950408889634f

// Scratch (static device arrays)
__device__ float g_a [NB*NL*ND];     // 1 MB
__device__ float g_bm[NB*NL*ND];     // 1 MB
__device__ float g_sc[NB*NL*NL];     // 4 MB scores -> softmax weights (in place)

__device__ __forceinline__ float tanh_fast(float x) {
    float y; asm("tanh.approx.f32 %0, %1;" : "=f"(y) : "f"(x)); return y;
}
__device__ __forceinline__ float ex2_fast(float x) {
    float y; asm("ex2.approx.ftz.f32 %0, %1;" : "=f"(y) : "f"(x)); return y;
}
__device__ __forceinline__ float rcp_fast(float x) {
    float y; asm("rcp.approx.ftz.f32 %0, %1;" : "=f"(y) : "f"(x)); return y;
}
__device__ __forceinline__ void cp_async16(unsigned int dst, const void* src) {
    asm volatile("cp.async.cg.shared.global [%0], [%1], 16;\n" :: "r"(dst), "l"(src));
}
__device__ __forceinline__ unsigned int smem_u32(const void* p) {
    unsigned int a;
    asm("{ .reg .u64 t; cvta.to.shared.u64 t, %1; cvt.u32.u64 %0, t; }" : "=r"(a) : "l"(p));
    return a;
}

// ---------------------------------------------------------------------------
// Kernel A: projections (transposed weight contraction):
//   a [bl][e] = sum_d hs[bl][d] * W_attn[e, d]
//   bm[bl][e] = sum_d hs[bl][d] * W_attn[e, 128 + d]
// ---------------------------------------------------------------------------
__global__ void proj_kernel(const float* __restrict__ hs,
                            const float* __restrict__ W) {
    __shared__ float hs_s[32 * 128];    // 16 KB
    __shared__ float W_s [128 * 64];    // 32 KB, [d][swizzled c]
    const int rowbase = blockIdx.x * 32;
    const int colbase = blockIdx.y * 64;
    const int tid = threadIdx.x;

    for (int k = tid; k < 32 * 128; k += 256)
        hs_s[k] = hs[(rowbase + (k >> 7)) * 128 + (k & 127)];
    for (int k = tid; k < 64 * 128; k += 256) {
        int c = k >> 7, d = k & 127;
        int e = colbase + c;
        float w = (e < 128) ? W[e * 256 + d] : W[(e - 128) * 256 + 128 + d];
        W_s[d * 64 + ((c + d) & 63)] = w;
    }
    __syncthreads();

    const int ty = tid >> 5, tx = tid & 31;
    float acc[4][2] = {};
#pragma unroll 4
    for (int k = 0; k < 128; k++) {
        float w0 = W_s[k * 64 + ((tx      + k) & 63)];
        float w1 = W_s[k * 64 + ((tx + 32 + k) & 63)];
#pragma unroll
        for (int rr = 0; rr < 4; rr++) {
            float h = hs_s[(ty * 4 + rr) * 128 + k];   // warp broadcast
            acc[rr][0] += h * w0;
            acc[rr][1] += h * w1;
        }
    }
#pragma unroll
    for (int rr = 0; rr < 4; rr++) {
        int row = rowbase + ty * 4 + rr;
#pragma unroll
        for (int cc = 0; cc < 2; cc++) {
            int e = colbase + tx + cc * 32;
            float val = acc[rr][cc];
            if (e < 128) g_a [row * 128 + e]         = val;
            else         g_bm[row * 128 + (e - 128)] = val;
        }
    }
}

// ---------------------------------------------------------------------------
// Kernel B (MUFU-bound): scores[b,i,j] = sum_d v[d]*tanh(a[b,i,d]+bm[b,j,d])
// grid (16,16,4), 256 threads, 2x2 micro-tile, float4 smem (pitch 33 vec4)
// ---------------------------------------------------------------------------
__global__ void score_kernel(const float* __restrict__ v) {
    __shared__ float4 a_s[32 * 33];     // 16.9 KB, row pitch 33 float4
    __shared__ float4 b_s[32 * 33];
    __shared__ float4 v_s[32];
    const int bi = blockIdx.z;
    const int i0 = blockIdx.x * 32, j0 = blockIdx.y * 32;
    const int tid = threadIdx.x;

    const float4* ga4 = (const float4*)g_a;
    const float4* gb4 = (const float4*)g_bm;
    for (int k = tid; k < 32 * 32; k += 256) {
        int r = k >> 5, q = k & 31;
        a_s[r * 33 + q] = ga4[(bi * NL + i0 + r) * 32 + q];
        b_s[r * 33 + q] = gb4[(bi * NL + j0 + r) * 32 + q];
    }
    if (tid < 32) v_s[tid] = ((const float4*)v)[tid];
    __syncthreads();

    const int ty = tid >> 4, tx = tid & 15;
    float acc00 = 0.f, acc01 = 0.f, acc10 = 0.f, acc11 = 0.f;
#pragma unroll 8
    for (int q = 0; q < 32; q++) {
        float4 vq = v_s[q];
        float4 a0 = a_s[ ty       * 33 + q];
        float4 a1 = a_s[(ty + 16) * 33 + q];
        float4 b0 = b_s[ tx       * 33 + q];
        float4 b1 = b_s[(tx + 16) * 33 + q];
        acc00 += vq.x * tanh_fast(a0.x + b0.x);
        acc00 += vq.y * tanh_fast(a0.y + b0.y);
        acc00 += vq.z * tanh_fast(a0.z + b0.z);
        acc00 += vq.w * tanh_fast(a0.w + b0.w);
        acc01 += vq.x * tanh_fast(a0.x + b1.x);
        acc01 += vq.y * tanh_fast(a0.y + b1.y);
        acc01 += vq.z * tanh_fast(a0.z + b1.z);
        acc01 += vq.w * tanh_fast(a0.w + b1.w);
        acc10 += vq.x * tanh_fast(a1.x + b0.x);
        acc10 += vq.y * tanh_fast(a1.y + b0.y);
        acc10 += vq.z * tanh_fast(a1.z + b0.z);
        acc10 += vq.w * tanh_fast(a1.w + b0.w);
        acc11 += vq.x * tanh_fast(a1.x + b1.x);
        acc11 += vq.y * tanh_fast(a1.y + b1.y);
        acc11 += vq.z * tanh_fast(a1.z + b1.z);
        acc11 += vq.w * tanh_fast(a1.w + b1.w);
    }
    float* sp = g_sc + (size_t)bi * NL * NL;
    sp[(i0 + ty     ) * NL + j0 + tx     ] = acc00;
    sp[(i0 + ty     ) * NL + j0 + tx + 16] = acc01;
    sp[(i0 + ty + 16) * NL + j0 + tx     ] = acc10;
    sp[(i0 + ty + 16) * NL + j0 + tx + 16] = acc11;
}

// ---------------------------------------------------------------------------
// Kernel C v2: full softmax over axis=1 (over i) per (b, j), IN PLACE.
// Pass 1: column max. Pass 2: sum of exp. Pass 3: overwrite g_sc with
// final weights ex2(s*L2E - ms) * inv. 512 threads: 32 j-lanes x 16 i-groups.
// grid (16, 4) = 64 blocks; each block owns 32 full columns -> race-free.
// ---------------------------------------------------------------------------
__global__ void stat_kernel() {
    const int bi = blockIdx.y;
    const int l  = threadIdx.x & 31;         // j lane
    const int g  = threadIdx.x >> 5;         // i-group 0..15
    const int j  = blockIdx.x * 32 + l;
    float* sp = g_sc + (size_t)bi * NL * NL + j;
    __shared__ float red[16][32];
    __shared__ float ms_sh[32], inv_sh[32];

    float m = -1e30f;
#pragma unroll 8
    for (int i = g; i < NL; i += 16) m = fmaxf(m, sp[i * NL]);
    red[g][l] = m;
    __syncthreads();
    if (g == 0) {
#pragma unroll
        for (int r = 1; r < 16; r++) m = fmaxf(m, red[r][l]);
        ms_sh[l] = m * L2E;
    }
    __syncthreads();
    const float ms = ms_sh[l];

    float s = 0.f;
#pragma unroll 8
    for (int i = g; i < NL; i += 16) s += ex2_fast(sp[i * NL] * L2E - ms);
    red[g][l] = s;
    __syncthreads();
    if (g == 0) {
#pragma unroll
        for (int r = 1; r < 16; r++) s += red[r][l];
        inv_sh[l] = rcp_fast(s);
    }
    __syncthreads();
    const float inv = inv_sh[l];

    // Pass 3: in-place normalize (each element owned by exactly one thread)
#pragma unroll 8
    for (int i = g; i < NL; i += 16)
        sp[i * NL] = ex2_fast(sp[i * NL] * L2E - ms) * inv;
}

// ---------------------------------------------------------------------------
// Kernel D v6: pure GEMM  out[b,i,d] = sum_j w[b,i,j] * hs[b,j,d]
// (w already fully normalized in g_sc). v3 fragment layout:
// Block 32 i x 64 d, 256 threads, grid (16,4,2) = 128.
// Warp covers 32 rows x 8 d; lane (r=lane>>1, c=lane&1): 2 rows x float4.
// Per j per warp: 1 LDS.64 w + 1 LDS.128 h + 8 FFMA.
// w staged transposed [j][row] pitch 34 via LDG->STS (plain copy, no math);
// h double-buffered via cp.async. smem 24.5 KB.
// ---------------------------------------------------------------------------
__global__ void __launch_bounds__(256, 2)
out_kernel(const float* __restrict__ hs, float* __restrict__ out) {
    __shared__ float w_s[2][32 * 34];                 // 8.5 KB  [j][row] pitch 34
    __shared__ __align__(16) float h_s[2][32 * 64];   // 16 KB   [j][d]
    const int i0 = blockIdx.x * 32;
    const int bi = blockIdx.y;
    const int d0 = blockIdx.z * 64;
    const int tid  = threadIdx.x;
    const int wid  = tid >> 5;
    const int lane = tid & 31;
    const int r = lane >> 1;          // row-pair index 0..15
    const int c = lane & 1;           // float4 column 0..1
    const int dfrag = wid * 8 + c * 4;

    const float* scb = g_sc + (size_t)bi * NL * NL;

    // ---- prologue: chunk 0 ----
    float rw[4];
#pragma unroll
    for (int s = 0; s < 4; s++) {
        int k = tid + 256 * s;                 // k = row*32 + j (coalesced over j)
        rw[s] = scb[(i0 + (k >> 5)) * NL + (k & 31)];
    }
#pragma unroll
    for (int s = 0; s < 2; s++) {
        int k = tid + 256 * s;                 // k = j*16 + seg
        int j = k >> 4, seg = k & 15;
        cp_async16(smem_u32(&h_s[0][j * 64 + seg * 4]),
                   &hs[(bi * NL + j) * ND + d0 + seg * 4]);
    }
    asm volatile("cp.async.commit_group;\n" ::: "memory");
#pragma unroll
    for (int s = 0; s < 4; s++) {
        int k = tid + 256 * s;
        int row = k >> 5, j = k & 31;
        w_s[0][j * 34 + row] = rw[s];
    }
    asm volatile("cp.async.wait_group 0;\n" ::: "memory");
    __syncthreads();

    float4 acc0 = make_float4(0.f, 0.f, 0.f, 0.f);
    float4 acc1 = make_float4(0.f, 0.f, 0.f, 0.f);

    int p = 0;
    for (int ch = 0; ch < 16; ch++) {
        const int jn = (ch + 1) * 32;
        if (ch < 15) {
            // prefetch next w tile (regs) + next h tile (cp.async, other buffer)
#pragma unroll
            for (int s = 0; s < 4; s++) {
                int k = tid + 256 * s;
                rw[s] = scb[(i0 + (k >> 5)) * NL + jn + (k & 31)];
            }
#pragma unroll
            for (int s = 0; s < 2; s++) {
                int k = tid + 256 * s;
                int j = k >> 4, seg = k & 15;
                cp_async16(smem_u32(&h_s[p ^ 1][j * 64 + seg * 4]),
                           &hs[(bi * NL + jn + j) * ND + d0 + seg * 4]);
            }
            asm volatile("cp.async.commit_group;\n" ::: "memory");
        }

        const float* wp = w_s[p];
        const float* hp = h_s[p];
#pragma unroll 8
        for (int j = 0; j < 32; j++) {
            float2 wf = *(const float2*)&wp[j * 34 + r * 2];   // 128B/warp
            float4 hf = *(const float4*)&hp[j * 64 + dfrag];   // 32B/warp
            acc0.x += wf.x * hf.x;  acc0.y += wf.x * hf.y;
            acc0.z += wf.x * hf.z;  acc0.w += wf.x * hf.w;
            acc1.x += wf.y * hf.x;  acc1.y += wf.y * hf.y;
            acc1.z += wf.y * hf.z;  acc1.w += wf.y * hf.w;
        }

        if (ch < 15) {
#pragma unroll
            for (int s = 0; s < 4; s++) {
                int k = tid + 256 * s;
                int row = k >> 5, j = k & 31;
                w_s[p ^ 1][j * 34 + row] = rw[s];
            }
            asm volatile("cp.async.wait_group 0;\n" ::: "memory");
            __syncthreads();
        }
        p ^= 1;
    }

    float* ob = out + ((size_t)bi * NL + i0 + r * 2) * ND + d0 + dfrag;
    *(float4*)&ob[0]  = acc0;
    *(float4*)&ob[ND] = acc1;
}

// ---------------------------------------------------------------------------
extern "C" void kernel_launch(void* const* d_in, const int* in_sizes, int n_in,
                              void* d_out, int out_size) {
    const float* hs = (const float*)d_in[0];   // (4,512,128)
    const float* W  = (const float*)d_in[1];   // (128,256)
    const float* v  = (const float*)d_in[2];   // (128,)
    float* out = (float*)d_out;                // (4,512,128)

    proj_kernel <<<dim3(64, 4),     256>>>(hs, W);
    score_kernel<<<dim3(16, 16, 4), 256>>>(v);
    stat_kernel <<<dim3(16, 4),     512>>>();
    out_kernel  <<<dim3(16, 4, 2),  256>>>(hs, out);
}

// round 11
// speedup vs baseline: 1.0914x; 1.0005x over previous
#include <cuda_runtime.h>
#include <cstdint>

#define NB 4
#define NL 512
#define ND 128
#define L2E 1.4426950408889634f

// Scratch (static device arrays)
__device__ float g_a [NB*NL*ND];     // 1 MB
__device__ float g_bm[NB*NL*ND];     // 1 MB
__device__ float g_sc[NB*NL*NL];     // 4 MB: exp(score) -> softmax weights (in place)

__device__ __forceinline__ float tanh_fast(float x) {
    float y; asm("tanh.approx.f32 %0, %1;" : "=f"(y) : "f"(x)); return y;
}
__device__ __forceinline__ float ex2_fast(float x) {
    float y; asm("ex2.approx.ftz.f32 %0, %1;" : "=f"(y) : "f"(x)); return y;
}
__device__ __forceinline__ float rcp_fast(float x) {
    float y; asm("rcp.approx.ftz.f32 %0, %1;" : "=f"(y) : "f"(x)); return y;
}
__device__ __forceinline__ void cp_async16(unsigned int dst, const void* src) {
    asm volatile("cp.async.cg.shared.global [%0], [%1], 16;\n" :: "r"(dst), "l"(src));
}
__device__ __forceinline__ unsigned int smem_u32(const void* p) {
    unsigned int a;
    asm("{ .reg .u64 t; cvta.to.shared.u64 t, %1; cvt.u32.u64 %0, t; }" : "=r"(a) : "l"(p));
    return a;
}

// ---------------------------------------------------------------------------
// Kernel A: projections (transposed weight contraction):
//   a [bl][e] = sum_d hs[bl][d] * W_attn[e, d]
//   bm[bl][e] = sum_d hs[bl][d] * W_attn[e, 128 + d]
// ---------------------------------------------------------------------------
__global__ void proj_kernel(const float* __restrict__ hs,
                            const float* __restrict__ W) {
    __shared__ float hs_s[32 * 128];    // 16 KB
    __shared__ float W_s [128 * 64];    // 32 KB, [d][swizzled c]
    const int rowbase = blockIdx.x * 32;
    const int colbase = blockIdx.y * 64;
    const int tid = threadIdx.x;

    for (int k = tid; k < 32 * 128; k += 256)
        hs_s[k] = hs[(rowbase + (k >> 7)) * 128 + (k & 127)];
    for (int k = tid; k < 64 * 128; k += 256) {
        int c = k >> 7, d = k & 127;
        int e = colbase + c;
        float w = (e < 128) ? W[e * 256 + d] : W[(e - 128) * 256 + 128 + d];
        W_s[d * 64 + ((c + d) & 63)] = w;
    }
    __syncthreads();

    const int ty = tid >> 5, tx = tid & 31;
    float acc[4][2] = {};
#pragma unroll 4
    for (int k = 0; k < 128; k++) {
        float w0 = W_s[k * 64 + ((tx      + k) & 63)];
        float w1 = W_s[k * 64 + ((tx + 32 + k) & 63)];
#pragma unroll
        for (int rr = 0; rr < 4; rr++) {
            float h = hs_s[(ty * 4 + rr) * 128 + k];   // warp broadcast
            acc[rr][0] += h * w0;
            acc[rr][1] += h * w1;
        }
    }
#pragma unroll
    for (int rr = 0; rr < 4; rr++) {
        int row = rowbase + ty * 4 + rr;
#pragma unroll
        for (int cc = 0; cc < 2; cc++) {
            int e = colbase + tx + cc * 32;
            float val = acc[rr][cc];
            if (e < 128) g_a [row * 128 + e]         = val;
            else         g_bm[row * 128 + (e - 128)] = val;
        }
    }
}

// ---------------------------------------------------------------------------
// Kernel B (MUFU-bound): writes E[b,i,j] = exp( sum_d v[d]*tanh(a+bm) ).
// No max subtraction needed: |score| <= sum|v| ~ 64, exp fits fp32 easily.
// grid (16,16,4), 256 threads, 2x2 micro-tile, float4 smem (pitch 33 vec4)
// ---------------------------------------------------------------------------
__global__ void score_kernel(const float* __restrict__ v) {
    __shared__ float4 a_s[32 * 33];     // 16.9 KB, row pitch 33 float4
    __shared__ float4 b_s[32 * 33];
    __shared__ float4 v_s[32];
    const int bi = blockIdx.z;
    const int i0 = blockIdx.x * 32, j0 = blockIdx.y * 32;
    const int tid = threadIdx.x;

    const float4* ga4 = (const float4*)g_a;
    const float4* gb4 = (const float4*)g_bm;
    for (int k = tid; k < 32 * 32; k += 256) {
        int r = k >> 5, q = k & 31;
        a_s[r * 33 + q] = ga4[(bi * NL + i0 + r) * 32 + q];
        b_s[r * 33 + q] = gb4[(bi * NL + j0 + r) * 32 + q];
    }
    if (tid < 32) v_s[tid] = ((const float4*)v)[tid];
    __syncthreads();

    const int ty = tid >> 4, tx = tid & 15;
    float acc00 = 0.f, acc01 = 0.f, acc10 = 0.f, acc11 = 0.f;
#pragma unroll 8
    for (int q = 0; q < 32; q++) {
        float4 vq = v_s[q];
        float4 a0 = a_s[ ty       * 33 + q];
        float4 a1 = a_s[(ty + 16) * 33 + q];
        float4 b0 = b_s[ tx       * 33 + q];
        float4 b1 = b_s[(tx + 16) * 33 + q];
        acc00 += vq.x * tanh_fast(a0.x + b0.x);
        acc00 += vq.y * tanh_fast(a0.y + b0.y);
        acc00 += vq.z * tanh_fast(a0.z + b0.z);
        acc00 += vq.w * tanh_fast(a0.w + b0.w);
        acc01 += vq.x * tanh_fast(a0.x + b1.x);
        acc01 += vq.y * tanh_fast(a0.y + b1.y);
        acc01 += vq.z * tanh_fast(a0.z + b1.z);
        acc01 += vq.w * tanh_fast(a0.w + b1.w);
        acc10 += vq.x * tanh_fast(a1.x + b0.x);
        acc10 += vq.y * tanh_fast(a1.y + b0.y);
        acc10 += vq.z * tanh_fast(a1.z + b0.z);
        acc10 += vq.w * tanh_fast(a1.w + b0.w);
        acc11 += vq.x * tanh_fast(a1.x + b1.x);
        acc11 += vq.y * tanh_fast(a1.y + b1.y);
        acc11 += vq.z * tanh_fast(a1.z + b1.z);
        acc11 += vq.w * tanh_fast(a1.w + b1.w);
    }
    float* sp = g_sc + (size_t)bi * NL * NL;
    sp[(i0 + ty     ) * NL + j0 + tx     ] = ex2_fast(acc00 * L2E);
    sp[(i0 + ty     ) * NL + j0 + tx + 16] = ex2_fast(acc01 * L2E);
    sp[(i0 + ty + 16) * NL + j0 + tx     ] = ex2_fast(acc10 * L2E);
    sp[(i0 + ty + 16) * NL + j0 + tx + 16] = ex2_fast(acc11 * L2E);
}

// ---------------------------------------------------------------------------
// Kernel C v3: 2-pass no-max softmax finish over axis=1 (i) per (b, j):
// pass 1 sums E down each column; pass 2 scales in place by 1/S.
// 512 threads: 32 j-lanes x 16 i-groups. grid (16,4); block owns 32 columns.
// ---------------------------------------------------------------------------
__global__ void stat_kernel() {
    const int bi = blockIdx.y;
    const int l  = threadIdx.x & 31;         // j lane
    const int g  = threadIdx.x >> 5;         // i-group 0..15
    const int j  = blockIdx.x * 32 + l;
    float* sp = g_sc + (size_t)bi * NL * NL + j;
    __shared__ float red[16][32];
    __shared__ float inv_sh[32];

    float s = 0.f;
#pragma unroll 8
    for (int i = g; i < NL; i += 16) s += sp[i * NL];
    red[g][l] = s;
    __syncthreads();
    if (g == 0) {
#pragma unroll
        for (int r = 1; r < 16; r++) s += red[r][l];
        inv_sh[l] = rcp_fast(s);
    }
    __syncthreads();
    const float inv = inv_sh[l];

#pragma unroll 8
    for (int i = g; i < NL; i += 16) sp[i * NL] *= inv;
}

// ---------------------------------------------------------------------------
// Kernel D v7: pure GEMM  out[b,i,d] = sum_j w[b,i,j] * hs[b,j,d]
// Same 8-FFMA fragment as v3/v6 but 128-thread CTAs covering 32 i x 32 d,
// grid (16,4,4) = 256 blocks -> all 148 SMs busy, ~2 CTAs/SM.
// Warp covers 32 rows x 8 d; lane (r=lane>>1, c=lane&1): 2 rows x float4.
// Per j per warp: 1 LDS.64 w + 1 LDS.128 h + 8 FFMA.
// w staged transposed [j][row] pitch 34 via LDG->STS; h double-buffered via
// cp.async. smem 16.7 KB.
// ---------------------------------------------------------------------------
__global__ void __launch_bounds__(128, 4)
out_kernel(const float* __restrict__ hs, float* __restrict__ out) {
    __shared__ float w_s[2][32 * 34];                 // 8.7 KB [j][row] pitch 34
    __shared__ __align__(16) float h_s[2][32 * 32];   // 8 KB   [j][d]
    const int i0 = blockIdx.x * 32;
    const int bi = blockIdx.y;
    const int d0 = blockIdx.z * 32;
    const int tid  = threadIdx.x;
    const int wid  = tid >> 5;        // 0..3
    const int lane = tid & 31;
    const int r = lane >> 1;          // row-pair index 0..15
    const int c = lane & 1;           // float4 column 0..1
    const int dfrag = wid * 8 + c * 4;

    const float* scb = g_sc + (size_t)bi * NL * NL;

    // ---- prologue: chunk 0 ----
    float rw[8];
#pragma unroll
    for (int s = 0; s < 8; s++) {
        int k = tid + 128 * s;                 // k = row*32 + j (coalesced over j)
        rw[s] = scb[(i0 + (k >> 5)) * NL + (k & 31)];
    }
#pragma unroll
    for (int s = 0; s < 2; s++) {
        int k = tid + 128 * s;                 // k = j*8 + seg  (32 d = 8 segs)
        int j = k >> 3, seg = k & 7;
        cp_async16(smem_u32(&h_s[0][j * 32 + seg * 4]),
                   &hs[(bi * NL + j) * ND + d0 + seg * 4]);
    }
    asm volatile("cp.async.commit_group;\n" ::: "memory");
#pragma unroll
    for (int s = 0; s < 8; s++) {
        int k = tid + 128 * s;
        int row = k >> 5, j = k & 31;
        w_s[0][j * 34 + row] = rw[s];
    }
    asm volatile("cp.async.wait_group 0;\n" ::: "memory");
    __syncthreads();

    float4 acc0 = make_float4(0.f, 0.f, 0.f, 0.f);
    float4 acc1 = make_float4(0.f, 0.f, 0.f, 0.f);

    int p = 0;
    for (int ch = 0; ch < 16; ch++) {
        const int jn = (ch + 1) * 32;
        if (ch < 15) {
            // prefetch next w tile (regs) + next h tile (cp.async, other buffer)
#pragma unroll
            for (int s = 0; s < 8; s++) {
                int k = tid + 128 * s;
                rw[s] = scb[(i0 + (k >> 5)) * NL + jn + (k & 31)];
            }
#pragma unroll
            for (int s = 0; s < 2; s++) {
                int k = tid + 128 * s;
                int j = k >> 3, seg = k & 7;
                cp_async16(smem_u32(&h_s[p ^ 1][j * 32 + seg * 4]),
                           &hs[(bi * NL + jn + j) * ND + d0 + seg * 4]);
            }
            asm volatile("cp.async.commit_group;\n" ::: "memory");
        }

        const float* wp = w_s[p];
        const float* hp = h_s[p];
#pragma unroll 8
        for (int j = 0; j < 32; j++) {
            float2 wf = *(const float2*)&wp[j * 34 + r * 2];   // 128B/warp
            float4 hf = *(const float4*)&hp[j * 32 + dfrag];   // 32B/warp
            acc0.x += wf.x * hf.x;  acc0.y += wf.x * hf.y;
            acc0.z += wf.x * hf.z;  acc0.w += wf.x * hf.w;
            acc1.x += wf.y * hf.x;  acc1.y += wf.y * hf.y;
            acc1.z += wf.y * hf.z;  acc1.w += wf.y * hf.w;
        }

        if (ch < 15) {
#pragma unroll
            for (int s = 0; s < 8; s++) {
                int k = tid + 128 * s;
                int row = k >> 5, j = k & 31;
                w_s[p ^ 1][j * 34 + row] = rw[s];
            }
            asm volatile("cp.async.wait_group 0;\n" ::: "memory");
            __syncthreads();
        }
        p ^= 1;
    }

    float* ob = out + ((size_t)bi * NL + i0 + r * 2) * ND + d0 + dfrag;
    *(float4*)&ob[0]  = acc0;
    *(float4*)&ob[ND] = acc1;
}

// ---------------------------------------------------------------------------
extern "C" void kernel_launch(void* const* d_in, const int* in_sizes, int n_in,
                              void* d_out, int out_size) {
    const float* hs = (const float*)d_in[0];   // (4,512,128)
    const float* W  = (const float*)d_in[1];   // (128,256)
    const float* v  = (const float*)d_in[2];   // (128,)
    float* out = (float*)d_out;                // (4,512,128)

    proj_kernel <<<dim3(64, 4),     256>>>(hs, W);
    score_kernel<<<dim3(16, 16, 4), 256>>>(v);
    stat_kernel <<<dim3(16, 4),     512>>>();
    out_kernel  <<<dim3(16, 4, 4),  128>>>(hs, out);
}

// round 12
// speedup vs baseline: 1.1255x; 1.0313x over previous
#include <cuda_runtime.h>
#include <cstdint>

#define NB 4
#define NL 512
#define ND 128
#define L2E 1.4426950408889634f

// Scratch (static device arrays)
__device__ float g_a [NB*NL*ND];     // 1 MB
__device__ float g_bm[NB*NL*ND];     // 1 MB
__device__ float g_sc[NB*NL*NL];     // 4 MB: exp(score), unnormalized
__device__ float g_ps[NB*16*NL];     // per (b, i-tile, j) partial column sums

__device__ __forceinline__ float tanh_fast(float x) {
    float y; asm("tanh.approx.f32 %0, %1;" : "=f"(y) : "f"(x)); return y;
}
__device__ __forceinline__ float ex2_fast(float x) {
    float y; asm("ex2.approx.ftz.f32 %0, %1;" : "=f"(y) : "f"(x)); return y;
}
__device__ __forceinline__ float rcp_fast(float x) {
    float y; asm("rcp.approx.ftz.f32 %0, %1;" : "=f"(y) : "f"(x)); return y;
}
__device__ __forceinline__ void cp_async16(unsigned int dst, const void* src) {
    asm volatile("cp.async.cg.shared.global [%0], [%1], 16;\n" :: "r"(dst), "l"(src));
}
__device__ __forceinline__ unsigned int smem_u32(const void* p) {
    unsigned int a;
    asm("{ .reg .u64 t; cvta.to.shared.u64 t, %1; cvt.u32.u64 %0, t; }" : "=r"(a) : "l"(p));
    return a;
}

// ---------------------------------------------------------------------------
// Kernel A: projections (transposed weight contraction):
//   a [bl][e] = sum_d hs[bl][d] * W_attn[e, d]
//   bm[bl][e] = sum_d hs[bl][d] * W_attn[e, 128 + d]
// ---------------------------------------------------------------------------
__global__ void proj_kernel(const float* __restrict__ hs,
                            const float* __restrict__ W) {
    __shared__ float hs_s[32 * 128];    // 16 KB
    __shared__ float W_s [128 * 64];    // 32 KB, [d][swizzled c]
    const int rowbase = blockIdx.x * 32;
    const int colbase = blockIdx.y * 64;
    const int tid = threadIdx.x;

    for (int k = tid; k < 32 * 128; k += 256)
        hs_s[k] = hs[(rowbase + (k >> 7)) * 128 + (k & 127)];
    for (int k = tid; k < 64 * 128; k += 256) {
        int c = k >> 7, d = k & 127;
        int e = colbase + c;
        float w = (e < 128) ? W[e * 256 + d] : W[(e - 128) * 256 + 128 + d];
        W_s[d * 64 + ((c + d) & 63)] = w;
    }
    __syncthreads();

    const int ty = tid >> 5, tx = tid & 31;
    float acc[4][2] = {};
#pragma unroll 4
    for (int k = 0; k < 128; k++) {
        float w0 = W_s[k * 64 + ((tx      + k) & 63)];
        float w1 = W_s[k * 64 + ((tx + 32 + k) & 63)];
#pragma unroll
        for (int rr = 0; rr < 4; rr++) {
            float h = hs_s[(ty * 4 + rr) * 128 + k];   // warp broadcast
            acc[rr][0] += h * w0;
            acc[rr][1] += h * w1;
        }
    }
#pragma unroll
    for (int rr = 0; rr < 4; rr++) {
        int row = rowbase + ty * 4 + rr;
#pragma unroll
        for (int cc = 0; cc < 2; cc++) {
            int e = colbase + tx + cc * 32;
            float val = acc[rr][cc];
            if (e < 128) g_a [row * 128 + e]         = val;
            else         g_bm[row * 128 + (e - 128)] = val;
        }
    }
}

// ---------------------------------------------------------------------------
// Kernel B (MUFU-bound): writes E[b,i,j] = exp( sum_d v[d]*tanh(a+bm) )
// (no max subtraction: |score| <= sum(v) ~ 64, exp fits fp32), plus a
// per-block partial column sum over its 32 i-rows -> g_ps[b][i_tile][j].
// grid (16,16,4), 256 threads, 2x2 micro-tile, float4 smem (pitch 33 vec4)
// ---------------------------------------------------------------------------
__global__ void score_kernel(const float* __restrict__ v) {
    __shared__ float4 a_s[32 * 33];     // 16.9 KB, row pitch 33 float4
    __shared__ float4 b_s[32 * 33];
    __shared__ float4 v_s[32];
    __shared__ float  cred[16][32];     // 2 KB column-sum reduction
    const int bi = blockIdx.z;
    const int i0 = blockIdx.x * 32, j0 = blockIdx.y * 32;
    const int tid = threadIdx.x;

    const float4* ga4 = (const float4*)g_a;
    const float4* gb4 = (const float4*)g_bm;
    for (int k = tid; k < 32 * 32; k += 256) {
        int r = k >> 5, q = k & 31;
        a_s[r * 33 + q] = ga4[(bi * NL + i0 + r) * 32 + q];
        b_s[r * 33 + q] = gb4[(bi * NL + j0 + r) * 32 + q];
    }
    if (tid < 32) v_s[tid] = ((const float4*)v)[tid];
    __syncthreads();

    const int ty = tid >> 4, tx = tid & 15;
    float acc00 = 0.f, acc01 = 0.f, acc10 = 0.f, acc11 = 0.f;
#pragma unroll 8
    for (int q = 0; q < 32; q++) {
        float4 vq = v_s[q];
        float4 a0 = a_s[ ty       * 33 + q];
        float4 a1 = a_s[(ty + 16) * 33 + q];
        float4 b0 = b_s[ tx       * 33 + q];
        float4 b1 = b_s[(tx + 16) * 33 + q];
        acc00 += vq.x * tanh_fast(a0.x + b0.x);
        acc00 += vq.y * tanh_fast(a0.y + b0.y);
        acc00 += vq.z * tanh_fast(a0.z + b0.z);
        acc00 += vq.w * tanh_fast(a0.w + b0.w);
        acc01 += vq.x * tanh_fast(a0.x + b1.x);
        acc01 += vq.y * tanh_fast(a0.y + b1.y);
        acc01 += vq.z * tanh_fast(a0.z + b1.z);
        acc01 += vq.w * tanh_fast(a0.w + b1.w);
        acc10 += vq.x * tanh_fast(a1.x + b0.x);
        acc10 += vq.y * tanh_fast(a1.y + b0.y);
        acc10 += vq.z * tanh_fast(a1.z + b0.z);
        acc10 += vq.w * tanh_fast(a1.w + b0.w);
        acc11 += vq.x * tanh_fast(a1.x + b1.x);
        acc11 += vq.y * tanh_fast(a1.y + b1.y);
        acc11 += vq.z * tanh_fast(a1.z + b1.z);
        acc11 += vq.w * tanh_fast(a1.w + b1.w);
    }
    float e00 = ex2_fast(acc00 * L2E);
    float e01 = ex2_fast(acc01 * L2E);
    float e10 = ex2_fast(acc10 * L2E);
    float e11 = ex2_fast(acc11 * L2E);

    float* sp = g_sc + (size_t)bi * NL * NL;
    sp[(i0 + ty     ) * NL + j0 + tx     ] = e00;
    sp[(i0 + ty     ) * NL + j0 + tx + 16] = e01;
    sp[(i0 + ty + 16) * NL + j0 + tx     ] = e10;
    sp[(i0 + ty + 16) * NL + j0 + tx + 16] = e11;

    // partial column sums over this block's 32 i-rows (fixed order -> determ.)
    cred[ty][tx]      = e00 + e10;
    cred[ty][tx + 16] = e01 + e11;
    __syncthreads();
    if (tid < 32) {
        float s = 0.f;
#pragma unroll
        for (int r2 = 0; r2 < 16; r2++) s += cred[r2][tid];
        g_ps[(bi * 16 + blockIdx.x) * NL + j0 + tid] = s;
    }
}

// ---------------------------------------------------------------------------
// Kernel C v8: out[b,i,d] = sum_j (E[b,i,j] * inv[b,j]) * hs[b,j,d]
// Preamble folds the 16 per-tile partial sums per column (fixed order),
// rcp -> inv_sh[512]; w staging multiplies by inv_sh (1 LDS + 1 FMUL extra).
// Same 8-FFMA fragment: 128-thread CTAs, 32 i x 32 d, grid (16,4,4)=256.
// Warp covers 32 rows x 8 d; lane (r=lane>>1, c=lane&1): 2 rows x float4.
// smem 18.9 KB.
// ---------------------------------------------------------------------------
__global__ void __launch_bounds__(128, 4)
out_kernel(const float* __restrict__ hs, float* __restrict__ out) {
    __shared__ float inv_sh[NL];                      // 2 KB
    __shared__ float w_s[2][32 * 34];                 // 8.7 KB [j][row] pitch 34
    __shared__ __align__(16) float h_s[2][32 * 32];   // 8 KB   [j][d]
    const int i0 = blockIdx.x * 32;
    const int bi = blockIdx.y;
    const int d0 = blockIdx.z * 32;
    const int tid  = threadIdx.x;
    const int wid  = tid >> 5;        // 0..3
    const int lane = tid & 31;
    const int r = lane >> 1;          // row-pair index 0..15
    const int c = lane & 1;           // float4 column 0..1
    const int dfrag = wid * 8 + c * 4;

    const float* scb = g_sc + (size_t)bi * NL * NL;

    // ---- preamble: column sums -> inverses ----
    for (int j = tid; j < NL; j += 128) {
        float s = 0.f;
#pragma unroll
        for (int it = 0; it < 16; it++)
            s += g_ps[(bi * 16 + it) * NL + j];
        inv_sh[j] = rcp_fast(s);
    }

    // ---- prologue: chunk 0 ----
    float rw[8];
#pragma unroll
    for (int s = 0; s < 8; s++) {
        int k = tid + 128 * s;                 // k = row*32 + j (coalesced over j)
        rw[s] = scb[(i0 + (k >> 5)) * NL + (k & 31)];
    }
#pragma unroll
    for (int s = 0; s < 2; s++) {
        int k = tid + 128 * s;                 // k = j*8 + seg  (32 d = 8 segs)
        int j = k >> 3, seg = k & 7;
        cp_async16(smem_u32(&h_s[0][j * 32 + seg * 4]),
                   &hs[(bi * NL + j) * ND + d0 + seg * 4]);
    }
    asm volatile("cp.async.commit_group;\n" ::: "memory");
    __syncthreads();                           // inv_sh visible
#pragma unroll
    for (int s = 0; s < 8; s++) {
        int k = tid + 128 * s;
        int row = k >> 5, j = k & 31;
        w_s[0][j * 34 + row] = rw[s] * inv_sh[j];
    }
    asm volatile("cp.async.wait_group 0;\n" ::: "memory");
    __syncthreads();

    float4 acc0 = make_float4(0.f, 0.f, 0.f, 0.f);
    float4 acc1 = make_float4(0.f, 0.f, 0.f, 0.f);

    int p = 0;
    for (int ch = 0; ch < 16; ch++) {
        const int jn = (ch + 1) * 32;
        if (ch < 15) {
            // prefetch next w tile (regs) + next h tile (cp.async, other buffer)
#pragma unroll
            for (int s = 0; s < 8; s++) {
                int k = tid + 128 * s;
                rw[s] = scb[(i0 + (k >> 5)) * NL + jn + (k & 31)];
            }
#pragma unroll
            for (int s = 0; s < 2; s++) {
                int k = tid + 128 * s;
                int j = k >> 3, seg = k & 7;
                cp_async16(smem_u32(&h_s[p ^ 1][j * 32 + seg * 4]),
                           &hs[(bi * NL + jn + j) * ND + d0 + seg * 4]);
            }
            asm volatile("cp.async.commit_group;\n" ::: "memory");
        }

        const float* wp = w_s[p];
        const float* hp = h_s[p];
#pragma unroll 8
        for (int j = 0; j < 32; j++) {
            float2 wf = *(const float2*)&wp[j * 34 + r * 2];   // 128B/warp
            float4 hf = *(const float4*)&hp[j * 32 + dfrag];   // 32B/warp
            acc0.x += wf.x * hf.x;  acc0.y += wf.x * hf.y;
            acc0.z += wf.x * hf.z;  acc0.w += wf.x * hf.w;
            acc1.x += wf.y * hf.x;  acc1.y += wf.y * hf.y;
            acc1.z += wf.y * hf.z;  acc1.w += wf.y * hf.w;
        }

        if (ch < 15) {
#pragma unroll
            for (int s = 0; s < 8; s++) {
                int k = tid + 128 * s;
                int row = k >> 5, j = k & 31;
                w_s[p ^ 1][j * 34 + row] = rw[s] * inv_sh[jn + j];
            }
            asm volatile("cp.async.wait_group 0;\n" ::: "memory");
            __syncthreads();
        }
        p ^= 1;
    }

    float* ob = out + ((size_t)bi * NL + i0 + r * 2) * ND + d0 + dfrag;
    *(float4*)&ob[0]  = acc0;
    *(float4*)&ob[ND] = acc1;
}

// ---------------------------------------------------------------------------
extern "C" void kernel_launch(void* const* d_in, const int* in_sizes, int n_in,
                              void* d_out, int out_size) {
    const float* hs = (const float*)d_in[0];   // (4,512,128)
    const float* W  = (const float*)d_in[1];   // (128,256)
    const float* v  = (const float*)d_in[2];   // (128,)
    float* out = (float*)d_out;                // (4,512,128)

    proj_kernel <<<dim3(64, 4),     256>>>(hs, W);
    score_kernel<<<dim3(16, 16, 4), 256>>>(v);
    out_kernel  <<<dim3(16, 4, 4),  128>>>(hs, out);
}

// round 13
// speedup vs baseline: 1.2412x; 1.1029x over previous
#include <cuda_runtime.h>
#include <cstdint>

#define NB 4
#define NL 512
#define ND 128
#define L2E 1.4426950408889634f

// Scratch (static device arrays)
__device__ float g_a [NB*NL*ND];     // 1 MB
__device__ float g_bm[NB*NL*ND];     // 1 MB
__device__ float g_sc[NB*NL*NL];     // 4 MB: exp(score), unnormalized
__device__ float g_ps[NB*16*NL];     // per (b, i-tile, j) partial column sums

__device__ __forceinline__ float tanh_fast(float x) {
    float y; asm("tanh.approx.f32 %0, %1;" : "=f"(y) : "f"(x)); return y;
}
__device__ __forceinline__ float ex2_fast(float x) {
    float y; asm("ex2.approx.ftz.f32 %0, %1;" : "=f"(y) : "f"(x)); return y;
}
__device__ __forceinline__ float rcp_fast(float x) {
    float y; asm("rcp.approx.ftz.f32 %0, %1;" : "=f"(y) : "f"(x)); return y;
}
__device__ __forceinline__ void cp_async16(unsigned int dst, const void* src) {
    asm volatile("cp.async.cg.shared.global [%0], [%1], 16;\n" :: "r"(dst), "l"(src));
}
__device__ __forceinline__ unsigned int smem_u32(const void* p) {
    unsigned int a;
    asm("{ .reg .u64 t; cvta.to.shared.u64 t, %1; cvt.u32.u64 %0, t; }" : "=r"(a) : "l"(p));
    return a;
}

// ---------------------------------------------------------------------------
// Kernel A v2: projections with out_kernel's fragment geometry.
//   e < 128 : a [row][e] = sum_d hs[row][d] * W[e, d]
//   e >= 128: bm[row][e-128] = sum_d hs[row][d] * W[e-128, 128+d]
// Block: 32 rows x 32 fused outputs, 128 threads, grid (64, 8) = 512 blocks.
// Warp = 32 rows x 8 outputs; thread = 2 rows x float4 of outputs.
// Per d: 2 LDS.32 row-frag (pitch 33, conflict-free) +
//        1 LDS.128 col-frag broadcast (pitch 36) + 8 FFMA.
// smem 35.3 KB, single sync, whole K resident.
// ---------------------------------------------------------------------------
__global__ void __launch_bounds__(128, 4)
proj_kernel(const float* __restrict__ hs, const float* __restrict__ W) {
    __shared__ float hs_t[128 * 33];                  // 16.9 KB [d][row]
    __shared__ __align__(16) float W_s[128 * 36];     // 18.4 KB [d][c]
    const int rowbase = blockIdx.x * 32;
    const int e0      = blockIdx.y * 32;              // fused output base (0..224)
    const int tid  = threadIdx.x;
    const int wid  = tid >> 5;
    const int lane = tid & 31;
    const int r = lane >> 1;          // row-pair index 0..15
    const int c = lane & 1;
    const int efrag = wid * 8 + c * 4;

    // Stage hs transposed: 32 iters, scalar coalesced load, stride-33 write
    // (33 mod 32 = 1 -> conflict-free STS).
    {
        const int dl = tid & 31;                // d lane within 32-chunk
        const int rw = tid >> 5;                // row group 0..3
#pragma unroll
        for (int it = 0; it < 8; it++) {
            int row = rw + it * 4;              // 0..31
#pragma unroll
            for (int dc = 0; dc < 4; dc++) {
                int d = dc * 32 + dl;
                hs_t[d * 33 + row] = hs[(rowbase + row) * 128 + d];
            }
        }
    }
    // Stage W: coalesced along d; W_s[d][c] pitch 36.
    {
#pragma unroll
        for (int it = 0; it < 32; it++) {
            int k = tid + 128 * it;             // k = cc*128 + d
            int cc = k >> 7, d = k & 127;
            int e = e0 + cc;
            float w = (e < 128) ? W[e * 256 + d]
                                : W[(e - 128) * 256 + 128 + d];
            W_s[d * 36 + cc] = w;
        }
    }
    __syncthreads();

    float4 acc0 = make_float4(0.f, 0.f, 0.f, 0.f);
    float4 acc1 = make_float4(0.f, 0.f, 0.f, 0.f);
#pragma unroll 4
    for (int d = 0; d < 128; d++) {
        float h0 = hs_t[d * 33 + r * 2];
        float h1 = hs_t[d * 33 + r * 2 + 1];
        float4 wf = *(const float4*)&W_s[d * 36 + efrag];   // broadcast
        acc0.x += h0 * wf.x;  acc0.y += h0 * wf.y;
        acc0.z += h0 * wf.z;  acc0.w += h0 * wf.w;
        acc1.x += h1 * wf.x;  acc1.y += h1 * wf.y;
        acc1.z += h1 * wf.z;  acc1.w += h1 * wf.w;
    }

    const int row0 = rowbase + r * 2;
    const int eg   = e0 + efrag;
    if (eg < 128) {
        *(float4*)&g_a[ row0      * 128 + eg] = acc0;
        *(float4*)&g_a[(row0 + 1) * 128 + eg] = acc1;
    } else {
        *(float4*)&g_bm[ row0      * 128 + eg - 128] = acc0;
        *(float4*)&g_bm[(row0 + 1) * 128 + eg - 128] = acc1;
    }
}

// ---------------------------------------------------------------------------
// Kernel B (MUFU-bound): writes E[b,i,j] = exp( sum_d v[d]*tanh(a+bm) )
// (no max subtraction: |score| <= sum(v) ~ 64, exp fits fp32), plus a
// per-block partial column sum over its 32 i-rows -> g_ps[b][i_tile][j].
// grid (16,16,4), 256 threads, 2x2 micro-tile, float4 smem (pitch 33 vec4)
// ---------------------------------------------------------------------------
__global__ void score_kernel(const float* __restrict__ v) {
    __shared__ float4 a_s[32 * 33];     // 16.9 KB, row pitch 33 float4
    __shared__ float4 b_s[32 * 33];
    __shared__ float4 v_s[32];
    __shared__ float  cred[16][32];     // 2 KB column-sum reduction
    const int bi = blockIdx.z;
    const int i0 = blockIdx.x * 32, j0 = blockIdx.y * 32;
    const int tid = threadIdx.x;

    const float4* ga4 = (const float4*)g_a;
    const float4* gb4 = (const float4*)g_bm;
    for (int k = tid; k < 32 * 32; k += 256) {
        int r = k >> 5, q = k & 31;
        a_s[r * 33 + q] = ga4[(bi * NL + i0 + r) * 32 + q];
        b_s[r * 33 + q] = gb4[(bi * NL + j0 + r) * 32 + q];
    }
    if (tid < 32) v_s[tid] = ((const float4*)v)[tid];
    __syncthreads();

    const int ty = tid >> 4, tx = tid & 15;
    float acc00 = 0.f, acc01 = 0.f, acc10 = 0.f, acc11 = 0.f;
#pragma unroll 8
    for (int q = 0; q < 32; q++) {
        float4 vq = v_s[q];
        float4 a0 = a_s[ ty       * 33 + q];
        float4 a1 = a_s[(ty + 16) * 33 + q];
        float4 b0 = b_s[ tx       * 33 + q];
        float4 b1 = b_s[(tx + 16) * 33 + q];
        acc00 += vq.x * tanh_fast(a0.x + b0.x);
        acc00 += vq.y * tanh_fast(a0.y + b0.y);
        acc00 += vq.z * tanh_fast(a0.z + b0.z);
        acc00 += vq.w * tanh_fast(a0.w + b0.w);
        acc01 += vq.x * tanh_fast(a0.x + b1.x);
        acc01 += vq.y * tanh_fast(a0.y + b1.y);
        acc01 += vq.z * tanh_fast(a0.z + b1.z);
        acc01 += vq.w * tanh_fast(a0.w + b1.w);
        acc10 += vq.x * tanh_fast(a1.x + b0.x);
        acc10 += vq.y * tanh_fast(a1.y + b0.y);
        acc10 += vq.z * tanh_fast(a1.z + b0.z);
        acc10 += vq.w * tanh_fast(a1.w + b0.w);
        acc11 += vq.x * tanh_fast(a1.x + b1.x);
        acc11 += vq.y * tanh_fast(a1.y + b1.y);
        acc11 += vq.z * tanh_fast(a1.z + b1.z);
        acc11 += vq.w * tanh_fast(a1.w + b1.w);
    }
    float e00 = ex2_fast(acc00 * L2E);
    float e01 = ex2_fast(acc01 * L2E);
    float e10 = ex2_fast(acc10 * L2E);
    float e11 = ex2_fast(acc11 * L2E);

    float* sp = g_sc + (size_t)bi * NL * NL;
    sp[(i0 + ty     ) * NL + j0 + tx     ] = e00;
    sp[(i0 + ty     ) * NL + j0 + tx + 16] = e01;
    sp[(i0 + ty + 16) * NL + j0 + tx     ] = e10;
    sp[(i0 + ty + 16) * NL + j0 + tx + 16] = e11;

    // partial column sums over this block's 32 i-rows (fixed order -> determ.)
    cred[ty][tx]      = e00 + e10;
    cred[ty][tx + 16] = e01 + e11;
    __syncthreads();
    if (tid < 32) {
        float s = 0.f;
#pragma unroll
        for (int r2 = 0; r2 < 16; r2++) s += cred[r2][tid];
        g_ps[(bi * 16 + blockIdx.x) * NL + j0 + tid] = s;
    }
}

// ---------------------------------------------------------------------------
// Kernel C v8: out[b,i,d] = sum_j (E[b,i,j] * inv[b,j]) * hs[b,j,d]
// Preamble folds the 16 per-tile partial sums per column (fixed order),
// rcp -> inv_sh[512]; w staging multiplies by inv_sh.
// 128-thread CTAs, 32 i x 32 d, grid (16,4,4)=256. smem 18.9 KB.
// ---------------------------------------------------------------------------
__global__ void __launch_bounds__(128, 4)
out_kernel(const float* __restrict__ hs, float* __restrict__ out) {
    __shared__ float inv_sh[NL];                      // 2 KB
    __shared__ float w_s[2][32 * 34];                 // 8.7 KB [j][row] pitch 34
    __shared__ __align__(16) float h_s[2][32 * 32];   // 8 KB   [j][d]
    const int i0 = blockIdx.x * 32;
    const int bi = blockIdx.y;
    const int d0 = blockIdx.z * 32;
    const int tid  = threadIdx.x;
    const int wid  = tid >> 5;        // 0..3
    const int lane = tid & 31;
    const int r = lane >> 1;          // row-pair index 0..15
    const int c = lane & 1;           // float4 column 0..1
    const int dfrag = wid * 8 + c * 4;

    const float* scb = g_sc + (size_t)bi * NL * NL;

    // ---- preamble: column sums -> inverses ----
    for (int j = tid; j < NL; j += 128) {
        float s = 0.f;
#pragma unroll
        for (int it = 0; it < 16; it++)
            s += g_ps[(bi * 16 + it) * NL + j];
        inv_sh[j] = rcp_fast(s);
    }

    // ---- prologue: chunk 0 ----
    float rw[8];
#pragma unroll
    for (int s = 0; s < 8; s++) {
        int k = tid + 128 * s;                 // k = row*32 + j (coalesced over j)
        rw[s] = scb[(i0 + (k >> 5)) * NL + (k & 31)];
    }
#pragma unroll
    for (int s = 0; s < 2; s++) {
        int k = tid + 128 * s;                 // k = j*8 + seg  (32 d = 8 segs)
        int j = k >> 3, seg = k & 7;
        cp_async16(smem_u32(&h_s[0][j * 32 + seg * 4]),
                   &hs[(bi * NL + j) * ND + d0 + seg * 4]);
    }
    asm volatile("cp.async.commit_group;\n" ::: "memory");
    __syncthreads();                           // inv_sh visible
#pragma unroll
    for (int s = 0; s < 8; s++) {
        int k = tid + 128 * s;
        int row = k >> 5, j = k & 31;
        w_s[0][j * 34 + row] = rw[s] * inv_sh[j];
    }
    asm volatile("cp.async.wait_group 0;\n" ::: "memory");
    __syncthreads();

    float4 acc0 = make_float4(0.f, 0.f, 0.f, 0.f);
    float4 acc1 = make_float4(0.f, 0.f, 0.f, 0.f);

    int p = 0;
    for (int ch = 0; ch < 16; ch++) {
        const int jn = (ch + 1) * 32;
        if (ch < 15) {
#pragma unroll
            for (int s = 0; s < 8; s++) {
                int k = tid + 128 * s;
                rw[s] = scb[(i0 + (k >> 5)) * NL + jn + (k & 31)];
            }
#pragma unroll
            for (int s = 0; s < 2; s++) {
                int k = tid + 128 * s;
                int j = k >> 3, seg = k & 7;
                cp_async16(smem_u32(&h_s[p ^ 1][j * 32 + seg * 4]),
                           &hs[(bi * NL + jn + j) * ND + d0 + seg * 4]);
            }
            asm volatile("cp.async.commit_group;\n" ::: "memory");
        }

        const float* wp = w_s[p];
        const float* hp = h_s[p];
#pragma unroll 8
        for (int j = 0; j < 32; j++) {
            float2 wf = *(const float2*)&wp[j * 34 + r * 2];   // 128B/warp
            float4 hf = *(const float4*)&hp[j * 32 + dfrag];   // 32B/warp
            acc0.x += wf.x * hf.x;  acc0.y += wf.x * hf.y;
            acc0.z += wf.x * hf.z;  acc0.w += wf.x * hf.w;
            acc1.x += wf.y * hf.x;  acc1.y += wf.y * hf.y;
            acc1.z += wf.y * hf.z;  acc1.w += wf.y * hf.w;
        }

        if (ch < 15) {
#pragma unroll
            for (int s = 0; s < 8; s++) {
                int k = tid + 128 * s;
                int row = k >> 5, j = k & 31;
                w_s[p ^ 1][j * 34 + row] = rw[s] * inv_sh[jn + j];
            }
            asm volatile("cp.async.wait_group 0;\n" ::: "memory");
            __syncthreads();
        }
        p ^= 1;
    }

    float* ob = out + ((size_t)bi * NL + i0 + r * 2) * ND + d0 + dfrag;
    *(float4*)&ob[0]  = acc0;
    *(float4*)&ob[ND] = acc1;
}

// ---------------------------------------------------------------------------
extern "C" void kernel_launch(void* const* d_in, const int* in_sizes, int n_in,
                              void* d_out, int out_size) {
    const float* hs = (const float*)d_in[0];   // (4,512,128)
    const float* W  = (const float*)d_in[1];   // (128,256)
    const float* v  = (const float*)d_in[2];   // (128,)
    float* out = (float*)d_out;                // (4,512,128)

    proj_kernel <<<dim3(64, 8),     128>>>(hs, W);
    score_kernel<<<dim3(16, 16, 4), 256>>>(v);
    out_kernel  <<<dim3(16, 4, 4),  128>>>(hs, out);
}